// round 15
// baseline (speedup 1.0000x reference)
#include <cuda_runtime.h>
#include <math.h>

#define NU 100000
#define NS 200000
#define DIMK 64
#define NH 2
#define HD 128          // NH * DIMK
#define BMAX 16384
#define NUW ((NU+31)/32)
#define NSW ((NS+31)/32)

#define TROWS 64        // rows per k_tail block
#define TTHREADS 256    // 8 warps; 8 rows x 4 cols per thread
#define WFULL (DIMK*HD)    // full GAT W floats (64x128 = 8192)

// ---------------- scratch (static device globals) -------------------------------
__device__ float g_acc_u[NU*HD];     // per-dst: sum ex * emb[src]  (head-major)
__device__ float g_acc_s[NS*HD];
__device__ float g_den_u[NU*NH];
__device__ float g_den_s[NS*NH];
__device__ float g_er_u[NU*NH];      // er for needed dsts, [node*2+h]
__device__ float g_er_s[NS*NH];
__device__ float g_wl_u[DIMK*NH];    // W @ a_l folded vectors, [k*2+h]
__device__ float g_wr_u[DIMK*NH];
__device__ float g_wl_s[DIMK*NH];
__device__ float g_wr_s[DIMK*NH];
__device__ unsigned g_needb_u[NUW];
__device__ unsigned g_needb_s[NSW];

// ---------------- helpers ------------------------------------------------------
__device__ __forceinline__ void red4(float* p, float a, float b, float c, float d) {
    asm volatile("{ .reg .u64 q; cvta.to.global.u64 q, %0;"
                 "  red.global.add.v4.f32 [q], {%1, %2, %3, %4}; }"
                 :: "l"(p), "f"(a), "f"(b), "f"(c), "f"(d) : "memory");
}

#define FCMP(v,kk) ((kk)==0?(v).x:((kk)==1?(v).y:((kk)==2?(v).z:(v).w)))

// ---------------- k_init: reset need bitmasks (blocks 0..N-2) + wvec (last) ----
__global__ void __launch_bounds__(256) k_init(const float* __restrict__ uW,
                                              const float* __restrict__ ual,
                                              const float* __restrict__ uar,
                                              const float* __restrict__ sW,
                                              const float* __restrict__ sal,
                                              const float* __restrict__ sar) {
    if (blockIdx.x == gridDim.x - 1) {
        int tid = threadIdx.x;            // 0..255
        int user = tid < 128;
        int t = tid & 127;
        int k = t >> 1, h = t & 1;
        const float* W  = user ? uW  : sW;
        const float* al = user ? ual : sal;
        const float* ar = user ? uar : sar;
        float accl = 0.f, accr = 0.f;
        #pragma unroll 8
        for (int d = 0; d < DIMK; d++) {
            float w = W[k*HD + h*DIMK + d];
            accl += w * al[h*DIMK + d];
            accr += w * ar[h*DIMK + d];
        }
        if (user) { g_wl_u[k*2+h] = accl; g_wr_u[k*2+h] = accr; }
        else      { g_wl_s[k*2+h] = accl; g_wr_s[k*2+h] = accr; }
        return;
    }
    int i = blockIdx.x*blockDim.x + threadIdx.x;
    int st = (gridDim.x-1)*blockDim.x;
    for (int j = i; j < NUW; j += st) g_needb_u[j] = 0u;
    for (int j = i; j < NSW; j += st) g_needb_s[j] = 0u;
}

// ---------------- k_mark: mark bits, zero acc/den, compute er for dsts ---------
__global__ void __launch_bounds__(128) k_mark(const int* __restrict__ uidx,
                                              const int* __restrict__ sidx,
                                              const float* __restrict__ uemb,
                                              const float* __restrict__ semb) {
    int b = blockIdx.x, t = threadIdx.x;
    int u = uidx[b], s = sidx[b];
    g_acc_u[u*HD + t] = 0.f;
    g_acc_s[s*HD + t] = 0.f;
    if (t < NH) { g_den_u[u*NH + t] = 0.f; g_den_s[s*NH + t] = 0.f; }
    if (t == 0) {
        atomicOr(&g_needb_u[u >> 5], 1u << (u & 31));
        atomicOr(&g_needb_s[s >> 5], 1u << (s & 31));
    }
    // er[d,h] = emb[d] . wr[:,h]; one warp per (side, head)
    {
        int wid = t >> 5, l = t & 31;
        int user = wid < 2, head = wid & 1;
        int node = user ? u : s;
        const float* emb = user ? uemb : semb;
        const float* wr  = user ? g_wr_u : g_wr_s;
        float* er        = user ? g_er_u : g_er_s;
        int k2 = l * 2;
        float2 ev = *(const float2*)&emb[(long long)node*DIMK + k2];
        float p = ev.x * __ldg(&wr[k2*2 + head]) + ev.y * __ldg(&wr[(k2+1)*2 + head]);
        #pragma unroll
        for (int o = 16; o; o >>= 1) p += __shfl_xor_sync(0xffffffffu, p, o);
        if (l == 0) er[node*NH + head] = p;
    }
}

// ---------------- k_edge_all: ballot-compact + HALF-WARP-per-edge drain --------
__global__ void __launch_bounds__(256) k_edge_all(const int* __restrict__ usrc,
                                                  const int* __restrict__ udst, int Eu,
                                                  const int* __restrict__ ssrc,
                                                  const int* __restrict__ sdst, int Es,
                                                  const float* __restrict__ uemb,
                                                  const float* __restrict__ semb,
                                                  int splitBlk) {
    int user = (blockIdx.x < splitBlk);
    const int* __restrict__ src = user ? usrc : ssrc;
    const int* __restrict__ dst = user ? udst : sdst;
    int E = user ? Eu : Es;
    const unsigned* __restrict__ needb = user ? g_needb_u : g_needb_s;
    const float* __restrict__ emb = user ? uemb : semb;
    const float* __restrict__ wl  = user ? g_wl_u : g_wl_s;
    const float* __restrict__ er  = user ? g_er_u : g_er_s;
    float* acc = user ? g_acc_u : g_acc_s;
    float* den = user ? g_den_u : g_den_s;
    int vb   = user ? blockIdx.x : blockIdx.x - splitBlk;
    int nblk = user ? splitBlk : gridDim.x - splitBlk;

    int tid = threadIdx.x;
    int wid = tid >> 5, l = tid & 31;
    int hl = l & 15;                   // lane in half-warp
    int lq = hl * 4;                   // this lane's 4 dims of the 64-dim row

    // folded attention weights for BOTH heads (8 regs)
    float wl00 = __ldg(&wl[(lq+0)*2 + 0]);
    float wl01 = __ldg(&wl[(lq+1)*2 + 0]);
    float wl02 = __ldg(&wl[(lq+2)*2 + 0]);
    float wl03 = __ldg(&wl[(lq+3)*2 + 0]);
    float wl10 = __ldg(&wl[(lq+0)*2 + 1]);
    float wl11 = __ldg(&wl[(lq+1)*2 + 1]);
    float wl12 = __ldg(&wl[(lq+2)*2 + 1]);
    float wl13 = __ldg(&wl[(lq+3)*2 + 1]);

    long long gwarp = (long long)vb*8 + wid;
    long long nwarp = (long long)nblk*8;

    for (long long base = gwarp*32; base < E; base += nwarp*32) {
        long long i = base + l;
        int d = 0, s = 0; bool m = false;
        if (i < E) {
            d = dst[i];
            m = (__ldg(&needb[d >> 5]) >> (d & 31)) & 1u;
        }
        unsigned bal = __ballot_sync(0xffffffffu, m);
        if (m) s = src[i];

        while (bal) {
            int b0 = __ffs(bal) - 1; bal &= bal - 1;
            bool has1 = (bal != 0);
            int b1 = has1 ? (__ffs(bal) - 1) : b0;
            if (has1) bal &= bal - 1;

            int myb = (l < 16) ? b0 : b1;
            int sS = __shfl_sync(0xffffffffu, s, myb);
            int dD = __shfl_sync(0xffffffffu, d, myb);

            float4 e = *(const float4*)&emb[(long long)sS * DIMK + lq];
            float2 erv = *(const float2*)&er[dD*NH];

            float p0 = e.x*wl00 + e.y*wl01 + e.z*wl02 + e.w*wl03;
            float p1 = e.x*wl10 + e.y*wl11 + e.z*wl12 + e.w*wl13;
            #pragma unroll
            for (int o = 8; o; o >>= 1) {      // reduce within 16-lane half
                p0 += __shfl_xor_sync(0xffffffffu, p0, o);
                p1 += __shfl_xor_sync(0xffffffffu, p1, o);
            }
            float a0 = p0 + erv.x;
            float a1 = p1 + erv.y;
            a0 = a0 > 0.f ? a0 : 0.2f * a0;    // leaky_relu(0.2)
            a1 = a1 > 0.f ? a1 : 0.2f * a1;
            float x0 = __expf(a0);             // softmax w/o max-shift (exact ratio)
            float x1 = __expf(a1);

            if ((l < 16) | has1) {
                red4(&acc[dD*HD + lq],        x0*e.x, x0*e.y, x0*e.z, x0*e.w);
                red4(&acc[dD*HD + DIMK + lq], x1*e.x, x1*e.y, x1*e.z, x1*e.w);
                if (hl == 0) {
                    atomicAdd(&den[dD*NH + 0], x0);
                    atomicAdd(&den[dD*NH + 1], x1);
                }
            }
        }
    }
}

// ---------------- k_tail: 64 rows/block, 256 thr, 8x4 tile per thread ----------
// One LDS.128 of W now feeds 32 FFMAs (was 16) -> crossbar no longer binding.
__global__ void __launch_bounds__(TTHREADS) k_tail(
        const int* __restrict__ uidx, const int* __restrict__ sidx,
        const float* __restrict__ uemb, const float* __restrict__ semb,
        const float* __restrict__ uW, const float* __restrict__ sW,
        const float* __restrict__ ubias, const float* __restrict__ ulng, const float* __restrict__ ulnb,
        const float* __restrict__ sbias, const float* __restrict__ slng, const float* __restrict__ slnb,
        const float* __restrict__ W1, const float* __restrict__ b1,
        const float* __restrict__ g1, const float* __restrict__ bb1,
        const float* __restrict__ W2, const float* __restrict__ b2,
        const float* __restrict__ g2, const float* __restrict__ bb2,
        const float* __restrict__ W3, const float* __restrict__ b3,
        float* __restrict__ out) {
    extern __shared__ float sm[];
    float* As   = sm;                    // TROWS*HD        (32 KB)
    float* xs   = As + TROWS*HD;         // TROWS*HD        (32 KB)
    float* Wbuf = xs + TROWS*HD;         // WFULL           (32 KB)
    int* nodes  = (int*)(Wbuf + WFULL);  // 2*TROWS

    int tid = threadIdx.x;
    int w = tid >> 5, l = tid & 31;      // 8 warps
    int rbase = blockIdx.x * TROWS;
    int r0 = w * 8, c0 = l * 4;          // 8 rows x 4 cols per thread
    int h = l >> 4;

    if (tid < TROWS)        nodes[tid] = uidx[rbase + tid];
    else if (tid < 2*TROWS) nodes[tid] = sidx[rbase + tid - TROWS];
    __syncthreads();

    // ================= GAT finalize per side =================
    #pragma unroll 1
    for (int side = 0; side < 2; side++) {
        const float* accp = side ? g_acc_s : g_acc_u;
        const float* denp = side ? g_den_s : g_den_u;
        const float* W    = side ? sW : uW;
        const float* bias = side ? sbias : ubias;
        const float* lng  = side ? slng : ulng;
        const float* lnb  = side ? slnb : ulnb;
        const float* emb  = side ? semb : uemb;

        // gather agg = acc * (1/den)  (TROWS x 128, float4)
        for (int i = tid; i < TROWS*(HD/4); i += TTHREADS) {
            int rr = i >> 5, cq = i & 31;
            int nd = nodes[side*TROWS + rr];
            float4 a4 = *(const float4*)&accp[(long long)nd*HD + cq*4];
            float inv = __fdividef(1.f, denp[nd*NH + (cq >> 4)]);
            *(float4*)&As[rr*HD + cq*4] = make_float4(a4.x*inv, a4.y*inv, a4.z*inv, a4.w*inv);
        }
        // stage FULL W (8192 floats: 8 float4 per thread)
        for (int i = tid; i < WFULL/4; i += TTHREADS)
            *(float4*)&Wbuf[i*4] = *(const float4*)&W[i*4];
        __syncthreads();

        float acc[8][4] = {};
        #pragma unroll 4
        for (int k = 0; k < DIMK; k++) {
            int ka = h*DIMK + k;
            float4 wv = *(const float4*)&Wbuf[k*HD + c0];
            #pragma unroll
            for (int r = 0; r < 8; r++) {
                float a = As[(r0+r)*HD + ka];
                acc[r][0] += a*wv.x; acc[r][1] += a*wv.y;
                acc[r][2] += a*wv.z; acc[r][3] += a*wv.w;
            }
        }

        float4 bv = *(const float4*)&bias[c0];
        float4 gv = *(const float4*)&lng[c0];
        float4 bb = *(const float4*)&lnb[c0];
        #pragma unroll
        for (int i = 0; i < 8; i++) {
            float v0 = acc[i][0] + bv.x, v1 = acc[i][1] + bv.y;
            float v2 = acc[i][2] + bv.z, v3 = acc[i][3] + bv.w;
            float sum = v0+v1+v2+v3;
            #pragma unroll
            for (int o = 16; o; o >>= 1) sum += __shfl_xor_sync(0xffffffffu, sum, o);
            float mean = sum * (1.f/HD);
            float d0 = v0-mean, d1 = v1-mean, d2 = v2-mean, d3 = v3-mean;
            float sq = d0*d0 + d1*d1 + d2*d2 + d3*d3;
            #pragma unroll
            for (int o = 16; o; o >>= 1) sq += __shfl_xor_sync(0xffffffffu, sq, o);
            float rstd = rsqrtf(sq * (1.f/HD) + 1e-5f);
            float n0 = d0*rstd*gv.x + bb.x;
            float n1 = d1*rstd*gv.y + bb.y;
            float n2 = d2*rstd*gv.z + bb.z;
            float n3 = d3*rstd*gv.w + bb.w;
            n0 = n0 > 0.f ? n0 : (__expf(n0) - 1.f);   // ELU
            n1 = n1 > 0.f ? n1 : (__expf(n1) - 1.f);
            n2 = n2 > 0.f ? n2 : (__expf(n2) - 1.f);
            n3 = n3 > 0.f ? n3 : (__expf(n3) - 1.f);
            // head-mean: lane l (<16) pairs with lane l+16 (col c vs c+64)
            float m0 = __shfl_xor_sync(0xffffffffu, n0, 16);
            float m1 = __shfl_xor_sync(0xffffffffu, n1, 16);
            float m2 = __shfl_xor_sync(0xffffffffu, n2, 16);
            float m3 = __shfl_xor_sync(0xffffffffu, n3, 16);
            if (l < 16) {
                int nd = nodes[side*TROWS + r0 + i];
                float4 e4 = *(const float4*)&emb[(long long)nd*DIMK + c0];
                float* xr = &xs[(r0+i)*HD + side*DIMK + c0];
                xr[0] = 0.5f*(n0+m0) + e4.x;
                xr[1] = 0.5f*(n1+m1) + e4.y;
                xr[2] = 0.5f*(n2+m2) + e4.z;
                xr[3] = 0.5f*(n3+m3) + e4.w;
            }
        }
        __syncthreads();   // As/Wbuf reuse safety for next phase
    }

    // ================= MLP: 128->128->128->1 =================
    const float* Wp[2]  = {W1, W2};
    const float* bp[2]  = {b1, b2};
    const float* gp[2]  = {g1, g2};
    const float* bbp[2] = {bb1, bb2};
    float val[8][4];

    #pragma unroll 1
    for (int layer = 0; layer < 2; layer++) {
        const float* W = Wp[layer];
        float acc[8][4] = {};
        #pragma unroll 1
        for (int kc = 0; kc < 2; kc++) {           // two 64-row halves of W
            for (int i = tid; i < WFULL/4; i += TTHREADS)
                *(float4*)&Wbuf[i*4] = *(const float4*)&W[kc*WFULL + i*4];
            __syncthreads();
            #pragma unroll 2
            for (int k4 = 0; k4 < DIMK; k4 += 4) {
                float4 A[8];
                #pragma unroll
                for (int r = 0; r < 8; r++)
                    A[r] = *(const float4*)&xs[(r0+r)*HD + kc*DIMK + k4];
                #pragma unroll
                for (int kk = 0; kk < 4; kk++) {
                    float4 wv = *(const float4*)&Wbuf[(k4+kk)*HD + c0];
                    #pragma unroll
                    for (int r = 0; r < 8; r++) {
                        float e = FCMP(A[r],kk);
                        acc[r][0] += e*wv.x; acc[r][1] += e*wv.y;
                        acc[r][2] += e*wv.z; acc[r][3] += e*wv.w;
                    }
                }
            }
            __syncthreads();                       // before Wbuf overwrite
        }

        float4 bv  = *(const float4*)&bp[layer][c0];
        float4 gv  = *(const float4*)&gp[layer][c0];
        float4 bbv = *(const float4*)&bbp[layer][c0];
        #pragma unroll
        for (int i = 0; i < 8; i++) {
            float a0 = acc[i][0] + bv.x, a1 = acc[i][1] + bv.y;
            float a2 = acc[i][2] + bv.z, a3 = acc[i][3] + bv.w;
            float sum = a0 + a1 + a2 + a3;
            #pragma unroll
            for (int o = 16; o; o >>= 1) sum += __shfl_xor_sync(0xffffffffu, sum, o);
            float mean = sum * (1.f/HD);
            float d0 = a0-mean, d1 = a1-mean, d2 = a2-mean, d3 = a3-mean;
            float sq = d0*d0 + d1*d1 + d2*d2 + d3*d3;
            #pragma unroll
            for (int o = 16; o; o >>= 1) sq += __shfl_xor_sync(0xffffffffu, sq, o);
            float rstd = rsqrtf(sq * (1.f/HD) + 1e-5f);
            float v0 = fmaxf(d0*rstd*gv.x + bbv.x, 0.f);
            float v1 = fmaxf(d1*rstd*gv.y + bbv.y, 0.f);
            float v2 = fmaxf(d2*rstd*gv.z + bbv.z, 0.f);
            float v3 = fmaxf(d3*rstd*gv.w + bbv.w, 0.f);
            val[i][0] = v0; val[i][1] = v1; val[i][2] = v2; val[i][3] = v3;
        }
        if (layer == 0) {
            #pragma unroll
            for (int i = 0; i < 8; i++) {
                float* xr = &xs[(r0+i)*HD + c0];
                xr[0] = val[i][0]; xr[1] = val[i][1]; xr[2] = val[i][2]; xr[3] = val[i][3];
            }
            __syncthreads();
        }
    }

    float4 w3 = *(const float4*)&W3[c0];
    float bias3 = b3[0];
    #pragma unroll
    for (int i = 0; i < 8; i++) {
        float p = val[i][0]*w3.x + val[i][1]*w3.y + val[i][2]*w3.z + val[i][3]*w3.w;
        #pragma unroll
        for (int o = 16; o; o >>= 1) p += __shfl_xor_sync(0xffffffffu, p, o);
        if (l == 0) out[rbase + r0 + i] = 1.f / (1.f + __expf(-(p + bias3)));
    }
}

// ---------------- launch --------------------------------------------------------
extern "C" void kernel_launch(void* const* d_in, const int* in_sizes, int n_in,
                              void* d_out, int out_size) {
    const int*   uidx  = (const int*)  d_in[0];
    const int*   sidx  = (const int*)  d_in[1];
    const int*   usrc  = (const int*)  d_in[2];
    const int*   udst  = (const int*)  d_in[3];
    const int*   ssrc  = (const int*)  d_in[4];
    const int*   sdst  = (const int*)  d_in[5];
    const float* uemb  = (const float*)d_in[6];
    const float* semb  = (const float*)d_in[7];
    const float* uW    = (const float*)d_in[8];
    const float* ual   = (const float*)d_in[9];
    const float* uar   = (const float*)d_in[10];
    const float* ubias = (const float*)d_in[11];
    const float* ulng  = (const float*)d_in[12];
    const float* ulnb  = (const float*)d_in[13];
    const float* sW    = (const float*)d_in[14];
    const float* sal   = (const float*)d_in[15];
    const float* sar   = (const float*)d_in[16];
    const float* sbias = (const float*)d_in[17];
    const float* slng  = (const float*)d_in[18];
    const float* slnb  = (const float*)d_in[19];
    const float* W1    = (const float*)d_in[20];
    const float* b1    = (const float*)d_in[21];
    const float* g1    = (const float*)d_in[22];
    const float* bb1   = (const float*)d_in[23];
    const float* W2    = (const float*)d_in[24];
    const float* b2    = (const float*)d_in[25];
    const float* g2    = (const float*)d_in[26];
    const float* bb2   = (const float*)d_in[27];
    const float* W3    = (const float*)d_in[28];
    const float* b3    = (const float*)d_in[29];
    float* out = (float*)d_out;

    int B  = in_sizes[0];
    int Eu = in_sizes[2];
    int Es = in_sizes[4];

    k_init<<<33, 256>>>(uW, ual, uar, sW, sal, sar);
    k_mark<<<B, 128>>>(uidx, sidx, uemb, semb);
    {
        int gu = 592, gs = 1184;   // split ~ Eu : Es
        k_edge_all<<<gu + gs, 256>>>(usrc, udst, Eu, ssrc, sdst, Es,
                                     uemb, semb, gu);
    }
    {
        const int smemBytes = (TROWS*HD + TROWS*HD + WFULL) * 4 + 2*TROWS*4;
        cudaFuncSetAttribute(k_tail, cudaFuncAttributeMaxDynamicSharedMemorySize, smemBytes);
        k_tail<<<(B + TROWS - 1)/TROWS, TTHREADS, smemBytes>>>(
            uidx, sidx, uemb, semb, uW, sW,
            ubias, ulng, ulnb, sbias, slng, slnb,
            W1, b1, g1, bb1, W2, b2, g2, bb2, W3, b3, out);
    }
}

// round 16
// speedup vs baseline: 1.0661x; 1.0661x over previous
#include <cuda_runtime.h>
#include <math.h>

#define NU 100000
#define NS 200000
#define DIMK 64
#define NH 2
#define HD 128          // NH * DIMK
#define BMAX 16384
#define NUW ((NU+31)/32)
#define NSW ((NS+31)/32)

#define TROWS 64        // rows per k_tail block
#define TTHREADS 512
#define WFULL (DIMK*HD)    // full GAT W floats (64x128 = 8192)

// ---------------- scratch (static device globals) -------------------------------
__device__ float g_acc_u[NU*HD];     // per-dst: sum ex * emb[src]  (head-major)
__device__ float g_acc_s[NS*HD];
__device__ float g_den_u[NU*NH];
__device__ float g_den_s[NS*NH];
__device__ float g_er_u[NU*NH];      // er for needed dsts, [node*2+h]
__device__ float g_er_s[NS*NH];
__device__ float g_wl_u[DIMK*NH];    // W @ a_l folded vectors, [k*2+h]
__device__ float g_wr_u[DIMK*NH];
__device__ float g_wl_s[DIMK*NH];
__device__ float g_wr_s[DIMK*NH];
__device__ unsigned g_needb_u[NUW];
__device__ unsigned g_needb_s[NSW];

// ---------------- helpers ------------------------------------------------------
__device__ __forceinline__ void red4(float* p, float a, float b, float c, float d) {
    asm volatile("{ .reg .u64 q; cvta.to.global.u64 q, %0;"
                 "  red.global.add.v4.f32 [q], {%1, %2, %3, %4}; }"
                 :: "l"(p), "f"(a), "f"(b), "f"(c), "f"(d) : "memory");
}

#define FCMP(v,kk) ((kk)==0?(v).x:((kk)==1?(v).y:((kk)==2?(v).z:(v).w)))

// ---------------- k_init: reset need bitmasks (blocks 0..N-2) + wvec (last) ----
__global__ void __launch_bounds__(256) k_init(const float* __restrict__ uW,
                                              const float* __restrict__ ual,
                                              const float* __restrict__ uar,
                                              const float* __restrict__ sW,
                                              const float* __restrict__ sal,
                                              const float* __restrict__ sar) {
    if (blockIdx.x == gridDim.x - 1) {
        int tid = threadIdx.x;            // 0..255
        int user = tid < 128;
        int t = tid & 127;
        int k = t >> 1, h = t & 1;
        const float* W  = user ? uW  : sW;
        const float* al = user ? ual : sal;
        const float* ar = user ? uar : sar;
        float accl = 0.f, accr = 0.f;
        #pragma unroll 8
        for (int d = 0; d < DIMK; d++) {
            float w = W[k*HD + h*DIMK + d];
            accl += w * al[h*DIMK + d];
            accr += w * ar[h*DIMK + d];
        }
        if (user) { g_wl_u[k*2+h] = accl; g_wr_u[k*2+h] = accr; }
        else      { g_wl_s[k*2+h] = accl; g_wr_s[k*2+h] = accr; }
        return;
    }
    int i = blockIdx.x*blockDim.x + threadIdx.x;
    int st = (gridDim.x-1)*blockDim.x;
    for (int j = i; j < NUW; j += st) g_needb_u[j] = 0u;
    for (int j = i; j < NSW; j += st) g_needb_s[j] = 0u;
}

// ---------------- k_mark v2: 8 batch elems per block ---------------------------
// float4 zero stores for acc rows, half-warp-per-(elem,side) er computation.
__global__ void __launch_bounds__(256) k_mark(const int* __restrict__ uidx,
                                              const int* __restrict__ sidx,
                                              const float* __restrict__ uemb,
                                              const float* __restrict__ semb) {
    __shared__ int nd[2][8];
    int tid = threadIdx.x;
    int rbase = blockIdx.x * 8;
    if (tid < 8)       nd[0][tid]     = uidx[rbase + tid];
    else if (tid < 16) nd[1][tid - 8] = sidx[rbase + tid - 8];
    __syncthreads();

    // zero acc rows: 8 elems x 2 sides x 32 float4 = 512 stores, 2 per thread
    #pragma unroll
    for (int j = tid; j < 512; j += 256) {
        int elem = j >> 6;
        int side = (j >> 5) & 1;
        int q = j & 31;
        float* acc = side ? g_acc_s : g_acc_u;
        int node = nd[side][elem];
        *(float4*)&acc[(long long)node*HD + q*4] = make_float4(0.f, 0.f, 0.f, 0.f);
    }
    // zero den + mark bits
    if (tid < 32) {
        int elem = tid >> 2;
        int side = (tid >> 1) & 1;
        int hh = tid & 1;
        int node = nd[side][elem];
        (side ? g_den_s : g_den_u)[node*NH + hh] = 0.f;
        if (hh == 0) {
            if (side) atomicOr(&g_needb_s[node >> 5], 1u << (node & 31));
            else      atomicOr(&g_needb_u[node >> 5], 1u << (node & 31));
        }
    }
    // er[d,h] = emb[d].wr[:,h]; half-warp per (elem, side), both heads
    {
        int hw = tid >> 4;               // 0..15
        int elem = hw >> 1, side = hw & 1;
        int hl = tid & 15;
        int node = nd[side][elem];
        const float* emb = side ? semb : uemb;
        const float* wr  = side ? g_wr_s : g_wr_u;
        float* er        = side ? g_er_s : g_er_u;
        int k0 = hl * 4;
        float4 e = *(const float4*)&emb[(long long)node*DIMK + k0];
        float p0 = e.x*__ldg(&wr[(k0+0)*2+0]) + e.y*__ldg(&wr[(k0+1)*2+0])
                 + e.z*__ldg(&wr[(k0+2)*2+0]) + e.w*__ldg(&wr[(k0+3)*2+0]);
        float p1 = e.x*__ldg(&wr[(k0+0)*2+1]) + e.y*__ldg(&wr[(k0+1)*2+1])
                 + e.z*__ldg(&wr[(k0+2)*2+1]) + e.w*__ldg(&wr[(k0+3)*2+1]);
        #pragma unroll
        for (int o = 8; o; o >>= 1) {    // reduce within 16-lane half
            p0 += __shfl_xor_sync(0xffffffffu, p0, o);
            p1 += __shfl_xor_sync(0xffffffffu, p1, o);
        }
        if (hl == 0) *(float2*)&er[node*NH] = make_float2(p0, p1);
    }
}

// ---------------- k_edge_all: ballot-compact + HALF-WARP-per-edge drain --------
__global__ void __launch_bounds__(256) k_edge_all(const int* __restrict__ usrc,
                                                  const int* __restrict__ udst, int Eu,
                                                  const int* __restrict__ ssrc,
                                                  const int* __restrict__ sdst, int Es,
                                                  const float* __restrict__ uemb,
                                                  const float* __restrict__ semb,
                                                  int splitBlk) {
    int user = (blockIdx.x < splitBlk);
    const int* __restrict__ src = user ? usrc : ssrc;
    const int* __restrict__ dst = user ? udst : sdst;
    int E = user ? Eu : Es;
    const unsigned* __restrict__ needb = user ? g_needb_u : g_needb_s;
    const float* __restrict__ emb = user ? uemb : semb;
    const float* __restrict__ wl  = user ? g_wl_u : g_wl_s;
    const float* __restrict__ er  = user ? g_er_u : g_er_s;
    float* acc = user ? g_acc_u : g_acc_s;
    float* den = user ? g_den_u : g_den_s;
    int vb   = user ? blockIdx.x : blockIdx.x - splitBlk;
    int nblk = user ? splitBlk : gridDim.x - splitBlk;

    int tid = threadIdx.x;
    int wid = tid >> 5, l = tid & 31;
    int hl = l & 15;                   // lane in half-warp
    int lq = hl * 4;                   // this lane's 4 dims of the 64-dim row

    // folded attention weights for BOTH heads (8 regs)
    float wl00 = __ldg(&wl[(lq+0)*2 + 0]);
    float wl01 = __ldg(&wl[(lq+1)*2 + 0]);
    float wl02 = __ldg(&wl[(lq+2)*2 + 0]);
    float wl03 = __ldg(&wl[(lq+3)*2 + 0]);
    float wl10 = __ldg(&wl[(lq+0)*2 + 1]);
    float wl11 = __ldg(&wl[(lq+1)*2 + 1]);
    float wl12 = __ldg(&wl[(lq+2)*2 + 1]);
    float wl13 = __ldg(&wl[(lq+3)*2 + 1]);

    long long gwarp = (long long)vb*8 + wid;
    long long nwarp = (long long)nblk*8;

    for (long long base = gwarp*32; base < E; base += nwarp*32) {
        long long i = base + l;
        int d = 0, s = 0; bool m = false;
        if (i < E) {
            d = dst[i];
            m = (__ldg(&needb[d >> 5]) >> (d & 31)) & 1u;
        }
        unsigned bal = __ballot_sync(0xffffffffu, m);
        if (m) s = src[i];

        while (bal) {
            int b0 = __ffs(bal) - 1; bal &= bal - 1;
            bool has1 = (bal != 0);
            int b1 = has1 ? (__ffs(bal) - 1) : b0;
            if (has1) bal &= bal - 1;

            int myb = (l < 16) ? b0 : b1;
            int sS = __shfl_sync(0xffffffffu, s, myb);
            int dD = __shfl_sync(0xffffffffu, d, myb);

            float4 e = *(const float4*)&emb[(long long)sS * DIMK + lq];
            float2 erv = *(const float2*)&er[dD*NH];

            float p0 = e.x*wl00 + e.y*wl01 + e.z*wl02 + e.w*wl03;
            float p1 = e.x*wl10 + e.y*wl11 + e.z*wl12 + e.w*wl13;
            #pragma unroll
            for (int o = 8; o; o >>= 1) {      // reduce within 16-lane half
                p0 += __shfl_xor_sync(0xffffffffu, p0, o);
                p1 += __shfl_xor_sync(0xffffffffu, p1, o);
            }
            float a0 = p0 + erv.x;
            float a1 = p1 + erv.y;
            a0 = a0 > 0.f ? a0 : 0.2f * a0;    // leaky_relu(0.2)
            a1 = a1 > 0.f ? a1 : 0.2f * a1;
            float x0 = __expf(a0);             // softmax w/o max-shift (exact ratio)
            float x1 = __expf(a1);

            if ((l < 16) | has1) {
                red4(&acc[dD*HD + lq],        x0*e.x, x0*e.y, x0*e.z, x0*e.w);
                red4(&acc[dD*HD + DIMK + lq], x1*e.x, x1*e.y, x1*e.z, x1*e.w);
                if (hl == 0) {
                    atomicAdd(&den[dD*NH + 0], x0);
                    atomicAdd(&den[dD*NH + 1], x1);
                }
            }
        }
    }
}

// ---------------- k_tail: 64 rows/block, 512 thr, FULL-matrix weight staging ---
__global__ void __launch_bounds__(TTHREADS) k_tail(
        const int* __restrict__ uidx, const int* __restrict__ sidx,
        const float* __restrict__ uemb, const float* __restrict__ semb,
        const float* __restrict__ uW, const float* __restrict__ sW,
        const float* __restrict__ ubias, const float* __restrict__ ulng, const float* __restrict__ ulnb,
        const float* __restrict__ sbias, const float* __restrict__ slng, const float* __restrict__ slnb,
        const float* __restrict__ W1, const float* __restrict__ b1,
        const float* __restrict__ g1, const float* __restrict__ bb1,
        const float* __restrict__ W2, const float* __restrict__ b2,
        const float* __restrict__ g2, const float* __restrict__ bb2,
        const float* __restrict__ W3, const float* __restrict__ b3,
        float* __restrict__ out) {
    extern __shared__ float sm[];
    float* As   = sm;                    // TROWS*HD        (32 KB)
    float* xs   = As + TROWS*HD;         // TROWS*HD        (32 KB)
    float* Wbuf = xs + TROWS*HD;         // WFULL           (32 KB)
    int* nodes  = (int*)(Wbuf + WFULL);  // 2*TROWS

    int tid = threadIdx.x;
    int w = tid >> 5, l = tid & 31;      // 16 warps
    int rbase = blockIdx.x * TROWS;
    int r0 = w * 4, c0 = l * 4;
    int h = l >> 4;

    if (tid < TROWS)        nodes[tid] = uidx[rbase + tid];
    else if (tid < 2*TROWS) nodes[tid] = sidx[rbase + tid - TROWS];
    __syncthreads();

    // ================= GAT finalize per side =================
    #pragma unroll 1
    for (int side = 0; side < 2; side++) {
        const float* accp = side ? g_acc_s : g_acc_u;
        const float* denp = side ? g_den_s : g_den_u;
        const float* W    = side ? sW : uW;
        const float* bias = side ? sbias : ubias;
        const float* lng  = side ? slng : ulng;
        const float* lnb  = side ? slnb : ulnb;
        const float* emb  = side ? semb : uemb;

        // gather agg = acc * (1/den)  (TROWS x 128, float4)
        for (int i = tid; i < TROWS*(HD/4); i += TTHREADS) {
            int rr = i >> 5, cq = i & 31;
            int nd = nodes[side*TROWS + rr];
            float4 a4 = *(const float4*)&accp[(long long)nd*HD + cq*4];
            float inv = __fdividef(1.f, denp[nd*NH + (cq >> 4)]);
            *(float4*)&As[rr*HD + cq*4] = make_float4(a4.x*inv, a4.y*inv, a4.z*inv, a4.w*inv);
        }
        // stage FULL W (8192 floats: 4 float4 per thread)
        #pragma unroll
        for (int c = 0; c < 4; c++)
            *(float4*)&Wbuf[c*2048 + tid*4] = *(const float4*)&W[c*2048 + tid*4];
        __syncthreads();

        float acc[4][4] = {};
        #pragma unroll 8
        for (int k = 0; k < DIMK; k++) {
            int ka = h*DIMK + k;
            float a0 = As[(r0+0)*HD + ka];
            float a1 = As[(r0+1)*HD + ka];
            float a2 = As[(r0+2)*HD + ka];
            float a3 = As[(r0+3)*HD + ka];
            float4 wv = *(const float4*)&Wbuf[k*HD + c0];
            acc[0][0] += a0*wv.x; acc[0][1] += a0*wv.y; acc[0][2] += a0*wv.z; acc[0][3] += a0*wv.w;
            acc[1][0] += a1*wv.x; acc[1][1] += a1*wv.y; acc[1][2] += a1*wv.z; acc[1][3] += a1*wv.w;
            acc[2][0] += a2*wv.x; acc[2][1] += a2*wv.y; acc[2][2] += a2*wv.z; acc[2][3] += a2*wv.w;
            acc[3][0] += a3*wv.x; acc[3][1] += a3*wv.y; acc[3][2] += a3*wv.z; acc[3][3] += a3*wv.w;
        }

        float4 bv = *(const float4*)&bias[c0];
        float4 gv = *(const float4*)&lng[c0];
        float4 bb = *(const float4*)&lnb[c0];
        #pragma unroll
        for (int i = 0; i < 4; i++) {
            float v0 = acc[i][0] + bv.x, v1 = acc[i][1] + bv.y;
            float v2 = acc[i][2] + bv.z, v3 = acc[i][3] + bv.w;
            float sum = v0+v1+v2+v3;
            #pragma unroll
            for (int o = 16; o; o >>= 1) sum += __shfl_xor_sync(0xffffffffu, sum, o);
            float mean = sum * (1.f/HD);
            float d0 = v0-mean, d1 = v1-mean, d2 = v2-mean, d3 = v3-mean;
            float sq = d0*d0 + d1*d1 + d2*d2 + d3*d3;
            #pragma unroll
            for (int o = 16; o; o >>= 1) sq += __shfl_xor_sync(0xffffffffu, sq, o);
            float rstd = rsqrtf(sq * (1.f/HD) + 1e-5f);
            float n0 = d0*rstd*gv.x + bb.x;
            float n1 = d1*rstd*gv.y + bb.y;
            float n2 = d2*rstd*gv.z + bb.z;
            float n3 = d3*rstd*gv.w + bb.w;
            n0 = n0 > 0.f ? n0 : (__expf(n0) - 1.f);   // ELU
            n1 = n1 > 0.f ? n1 : (__expf(n1) - 1.f);
            n2 = n2 > 0.f ? n2 : (__expf(n2) - 1.f);
            n3 = n3 > 0.f ? n3 : (__expf(n3) - 1.f);
            // head-mean: lane l (<16) pairs with lane l+16 (col c vs c+64)
            float m0 = __shfl_xor_sync(0xffffffffu, n0, 16);
            float m1 = __shfl_xor_sync(0xffffffffu, n1, 16);
            float m2 = __shfl_xor_sync(0xffffffffu, n2, 16);
            float m3 = __shfl_xor_sync(0xffffffffu, n3, 16);
            if (l < 16) {
                int nd = nodes[side*TROWS + r0 + i];
                float4 e4 = *(const float4*)&emb[(long long)nd*DIMK + c0];
                float* xr = &xs[(r0+i)*HD + side*DIMK + c0];
                xr[0] = 0.5f*(n0+m0) + e4.x;
                xr[1] = 0.5f*(n1+m1) + e4.y;
                xr[2] = 0.5f*(n2+m2) + e4.z;
                xr[3] = 0.5f*(n3+m3) + e4.w;
            }
        }
        __syncthreads();   // As/Wbuf reuse safety for next phase
    }

    // ================= MLP: 128->128->128->1 =================
    const float* Wp[2]  = {W1, W2};
    const float* bp[2]  = {b1, b2};
    const float* gp[2]  = {g1, g2};
    const float* bbp[2] = {bb1, bb2};
    float val[4][4];

    #pragma unroll 1
    for (int layer = 0; layer < 2; layer++) {
        const float* W = Wp[layer];
        float acc[4][4] = {};
        #pragma unroll 1
        for (int kc = 0; kc < 2; kc++) {           // two 64-row halves of W
            #pragma unroll
            for (int c = 0; c < 4; c++)
                *(float4*)&Wbuf[c*2048 + tid*4] = *(const float4*)&W[kc*WFULL + c*2048 + tid*4];
            __syncthreads();
            #pragma unroll 4
            for (int k4 = 0; k4 < DIMK; k4 += 4) {
                float4 A0 = *(const float4*)&xs[(r0+0)*HD + kc*DIMK + k4];
                float4 A1 = *(const float4*)&xs[(r0+1)*HD + kc*DIMK + k4];
                float4 A2 = *(const float4*)&xs[(r0+2)*HD + kc*DIMK + k4];
                float4 A3 = *(const float4*)&xs[(r0+3)*HD + kc*DIMK + k4];
                #pragma unroll
                for (int kk = 0; kk < 4; kk++) {
                    float4 wv = *(const float4*)&Wbuf[(k4+kk)*HD + c0];
                    float e0 = FCMP(A0,kk), e1 = FCMP(A1,kk), e2 = FCMP(A2,kk), e3 = FCMP(A3,kk);
                    acc[0][0] += e0*wv.x; acc[0][1] += e0*wv.y; acc[0][2] += e0*wv.z; acc[0][3] += e0*wv.w;
                    acc[1][0] += e1*wv.x; acc[1][1] += e1*wv.y; acc[1][2] += e1*wv.z; acc[1][3] += e1*wv.w;
                    acc[2][0] += e2*wv.x; acc[2][1] += e2*wv.y; acc[2][2] += e2*wv.z; acc[2][3] += e2*wv.w;
                    acc[3][0] += e3*wv.x; acc[3][1] += e3*wv.y; acc[3][2] += e3*wv.z; acc[3][3] += e3*wv.w;
                }
            }
            __syncthreads();                       // before Wbuf overwrite
        }

        float4 bv  = *(const float4*)&bp[layer][c0];
        float4 gv  = *(const float4*)&gp[layer][c0];
        float4 bbv = *(const float4*)&bbp[layer][c0];
        #pragma unroll
        for (int i = 0; i < 4; i++) {
            float a0 = acc[i][0] + bv.x, a1 = acc[i][1] + bv.y;
            float a2 = acc[i][2] + bv.z, a3 = acc[i][3] + bv.w;
            float sum = a0 + a1 + a2 + a3;
            #pragma unroll
            for (int o = 16; o; o >>= 1) sum += __shfl_xor_sync(0xffffffffu, sum, o);
            float mean = sum * (1.f/HD);
            float d0 = a0-mean, d1 = a1-mean, d2 = a2-mean, d3 = a3-mean;
            float sq = d0*d0 + d1*d1 + d2*d2 + d3*d3;
            #pragma unroll
            for (int o = 16; o; o >>= 1) sq += __shfl_xor_sync(0xffffffffu, sq, o);
            float rstd = rsqrtf(sq * (1.f/HD) + 1e-5f);
            float v0 = fmaxf(d0*rstd*gv.x + bbv.x, 0.f);
            float v1 = fmaxf(d1*rstd*gv.y + bbv.y, 0.f);
            float v2 = fmaxf(d2*rstd*gv.z + bbv.z, 0.f);
            float v3 = fmaxf(d3*rstd*gv.w + bbv.w, 0.f);
            val[i][0] = v0; val[i][1] = v1; val[i][2] = v2; val[i][3] = v3;
        }
        if (layer == 0) {
            #pragma unroll
            for (int i = 0; i < 4; i++) {
                float* xr = &xs[(r0+i)*HD + c0];
                xr[0] = val[i][0]; xr[1] = val[i][1]; xr[2] = val[i][2]; xr[3] = val[i][3];
            }
            __syncthreads();
        }
    }

    float4 w3 = *(const float4*)&W3[c0];
    float bias3 = b3[0];
    #pragma unroll
    for (int i = 0; i < 4; i++) {
        float p = val[i][0]*w3.x + val[i][1]*w3.y + val[i][2]*w3.z + val[i][3]*w3.w;
        #pragma unroll
        for (int o = 16; o; o >>= 1) p += __shfl_xor_sync(0xffffffffu, p, o);
        if (l == 0) out[rbase + r0 + i] = 1.f / (1.f + __expf(-(p + bias3)));
    }
}

// ---------------- launch --------------------------------------------------------
extern "C" void kernel_launch(void* const* d_in, const int* in_sizes, int n_in,
                              void* d_out, int out_size) {
    const int*   uidx  = (const int*)  d_in[0];
    const int*   sidx  = (const int*)  d_in[1];
    const int*   usrc  = (const int*)  d_in[2];
    const int*   udst  = (const int*)  d_in[3];
    const int*   ssrc  = (const int*)  d_in[4];
    const int*   sdst  = (const int*)  d_in[5];
    const float* uemb  = (const float*)d_in[6];
    const float* semb  = (const float*)d_in[7];
    const float* uW    = (const float*)d_in[8];
    const float* ual   = (const float*)d_in[9];
    const float* uar   = (const float*)d_in[10];
    const float* ubias = (const float*)d_in[11];
    const float* ulng  = (const float*)d_in[12];
    const float* ulnb  = (const float*)d_in[13];
    const float* sW    = (const float*)d_in[14];
    const float* sal   = (const float*)d_in[15];
    const float* sar   = (const float*)d_in[16];
    const float* sbias = (const float*)d_in[17];
    const float* slng  = (const float*)d_in[18];
    const float* slnb  = (const float*)d_in[19];
    const float* W1    = (const float*)d_in[20];
    const float* b1    = (const float*)d_in[21];
    const float* g1    = (const float*)d_in[22];
    const float* bb1   = (const float*)d_in[23];
    const float* W2    = (const float*)d_in[24];
    const float* b2    = (const float*)d_in[25];
    const float* g2    = (const float*)d_in[26];
    const float* bb2   = (const float*)d_in[27];
    const float* W3    = (const float*)d_in[28];
    const float* b3    = (const float*)d_in[29];
    float* out = (float*)d_out;

    int B  = in_sizes[0];
    int Eu = in_sizes[2];
    int Es = in_sizes[4];

    k_init<<<33, 256>>>(uW, ual, uar, sW, sal, sar);
    k_mark<<<B/8, 256>>>(uidx, sidx, uemb, semb);
    {
        int gu = 592, gs = 1184;   // split ~ Eu : Es
        k_edge_all<<<gu + gs, 256>>>(usrc, udst, Eu, ssrc, sdst, Es,
                                     uemb, semb, gu);
    }
    {
        const int smemBytes = (TROWS*HD + TROWS*HD + WFULL) * 4 + 2*TROWS*4;
        cudaFuncSetAttribute(k_tail, cudaFuncAttributeMaxDynamicSharedMemorySize, smemBytes);
        k_tail<<<(B + TROWS - 1)/TROWS, TTHREADS, smemBytes>>>(
            uidx, sidx, uemb, semb, uW, sW,
            ubias, ulng, ulnb, sbias, slng, slnb,
            W1, b1, g1, bb1, W2, b2, g2, bb2, W3, b3, out);
    }
}

// round 17
// speedup vs baseline: 1.0823x; 1.0152x over previous
#include <cuda_runtime.h>
#include <math.h>

#define NU 100000
#define NS 200000
#define DIMK 64
#define NH 2
#define HD 128          // NH * DIMK
#define BMAX 16384
#define NUW ((NU+31)/32)
#define NSW ((NS+31)/32)

#define TROWS 64        // rows per k_tail block
#define TTHREADS 512
#define WFULL (DIMK*HD)    // full GAT W floats (64x128 = 8192)

// ---------------- scratch (static device globals) -------------------------------
__device__ float g_acc_u[NU*HD];     // per-dst: sum ex * emb[src]  (head-major)
__device__ float g_acc_s[NS*HD];
__device__ float g_den_u[NU*NH];
__device__ float g_den_s[NS*NH];
__device__ float g_er_u[NU*NH];      // er for needed dsts, [node*2+h]
__device__ float g_er_s[NS*NH];
__device__ float g_wl_u[DIMK*NH];    // W @ a_l folded vectors, [k*2+h]
__device__ float g_wr_u[DIMK*NH];
__device__ float g_wl_s[DIMK*NH];
__device__ float g_wr_s[DIMK*NH];
__device__ unsigned g_needb_u[NUW];
__device__ unsigned g_needb_s[NSW];

// ---------------- helpers ------------------------------------------------------
__device__ __forceinline__ void red4(float* p, float a, float b, float c, float d) {
    asm volatile("{ .reg .u64 q; cvta.to.global.u64 q, %0;"
                 "  red.global.add.v4.f32 [q], {%1, %2, %3, %4}; }"
                 :: "l"(p), "f"(a), "f"(b), "f"(c), "f"(d) : "memory");
}

#define FCMP(v,kk) ((kk)==0?(v).x:((kk)==1?(v).y:((kk)==2?(v).z:(v).w)))

// packed f32x2 FMA (sm_103a; ptxas never auto-fuses — PTX only)
__device__ __forceinline__ void ffma2(unsigned long long& d,
                                      unsigned long long a,
                                      unsigned long long b) {
    asm("fma.rn.f32x2 %0, %1, %2, %0;" : "+l"(d) : "l"(a), "l"(b));
}
__device__ __forceinline__ unsigned long long pack2(float x, float y) {
    unsigned long long r;
    asm("mov.b64 %0, {%1, %2};" : "=l"(r) : "f"(x), "f"(y));
    return r;
}
__device__ __forceinline__ float2 unpack2(unsigned long long v) {
    float2 r;
    asm("mov.b64 {%0, %1}, %2;" : "=f"(r.x), "=f"(r.y) : "l"(v));
    return r;
}

// ---------------- k_init: reset need bitmasks (blocks 0..N-2) + wvec (last) ----
__global__ void __launch_bounds__(256) k_init(const float* __restrict__ uW,
                                              const float* __restrict__ ual,
                                              const float* __restrict__ uar,
                                              const float* __restrict__ sW,
                                              const float* __restrict__ sal,
                                              const float* __restrict__ sar) {
    if (blockIdx.x == gridDim.x - 1) {
        int tid = threadIdx.x;            // 0..255
        int user = tid < 128;
        int t = tid & 127;
        int k = t >> 1, h = t & 1;
        const float* W  = user ? uW  : sW;
        const float* al = user ? ual : sal;
        const float* ar = user ? uar : sar;
        float accl = 0.f, accr = 0.f;
        #pragma unroll 8
        for (int d = 0; d < DIMK; d++) {
            float w = W[k*HD + h*DIMK + d];
            accl += w * al[h*DIMK + d];
            accr += w * ar[h*DIMK + d];
        }
        if (user) { g_wl_u[k*2+h] = accl; g_wr_u[k*2+h] = accr; }
        else      { g_wl_s[k*2+h] = accl; g_wr_s[k*2+h] = accr; }
        return;
    }
    int i = blockIdx.x*blockDim.x + threadIdx.x;
    int st = (gridDim.x-1)*blockDim.x;
    for (int j = i; j < NUW; j += st) g_needb_u[j] = 0u;
    for (int j = i; j < NSW; j += st) g_needb_s[j] = 0u;
}

// ---------------- k_mark: 8 batch elems per block ------------------------------
__global__ void __launch_bounds__(256) k_mark(const int* __restrict__ uidx,
                                              const int* __restrict__ sidx,
                                              const float* __restrict__ uemb,
                                              const float* __restrict__ semb) {
    __shared__ int nd[2][8];
    int tid = threadIdx.x;
    int rbase = blockIdx.x * 8;
    if (tid < 8)       nd[0][tid]     = uidx[rbase + tid];
    else if (tid < 16) nd[1][tid - 8] = sidx[rbase + tid - 8];
    __syncthreads();

    #pragma unroll
    for (int j = tid; j < 512; j += 256) {
        int elem = j >> 6;
        int side = (j >> 5) & 1;
        int q = j & 31;
        float* acc = side ? g_acc_s : g_acc_u;
        int node = nd[side][elem];
        *(float4*)&acc[(long long)node*HD + q*4] = make_float4(0.f, 0.f, 0.f, 0.f);
    }
    if (tid < 32) {
        int elem = tid >> 2;
        int side = (tid >> 1) & 1;
        int hh = tid & 1;
        int node = nd[side][elem];
        (side ? g_den_s : g_den_u)[node*NH + hh] = 0.f;
        if (hh == 0) {
            if (side) atomicOr(&g_needb_s[node >> 5], 1u << (node & 31));
            else      atomicOr(&g_needb_u[node >> 5], 1u << (node & 31));
        }
    }
    {
        int hw = tid >> 4;               // 0..15
        int elem = hw >> 1, side = hw & 1;
        int hl = tid & 15;
        int node = nd[side][elem];
        const float* emb = side ? semb : uemb;
        const float* wr  = side ? g_wr_s : g_wr_u;
        float* er        = side ? g_er_s : g_er_u;
        int k0 = hl * 4;
        float4 e = *(const float4*)&emb[(long long)node*DIMK + k0];
        float p0 = e.x*__ldg(&wr[(k0+0)*2+0]) + e.y*__ldg(&wr[(k0+1)*2+0])
                 + e.z*__ldg(&wr[(k0+2)*2+0]) + e.w*__ldg(&wr[(k0+3)*2+0]);
        float p1 = e.x*__ldg(&wr[(k0+0)*2+1]) + e.y*__ldg(&wr[(k0+1)*2+1])
                 + e.z*__ldg(&wr[(k0+2)*2+1]) + e.w*__ldg(&wr[(k0+3)*2+1]);
        #pragma unroll
        for (int o = 8; o; o >>= 1) {
            p0 += __shfl_xor_sync(0xffffffffu, p0, o);
            p1 += __shfl_xor_sync(0xffffffffu, p1, o);
        }
        if (hl == 0) *(float2*)&er[node*NH] = make_float2(p0, p1);
    }
}

// ---------------- k_edge_all: ballot-compact + HALF-WARP-per-edge drain --------
__global__ void __launch_bounds__(256) k_edge_all(const int* __restrict__ usrc,
                                                  const int* __restrict__ udst, int Eu,
                                                  const int* __restrict__ ssrc,
                                                  const int* __restrict__ sdst, int Es,
                                                  const float* __restrict__ uemb,
                                                  const float* __restrict__ semb,
                                                  int splitBlk) {
    int user = (blockIdx.x < splitBlk);
    const int* __restrict__ src = user ? usrc : ssrc;
    const int* __restrict__ dst = user ? udst : sdst;
    int E = user ? Eu : Es;
    const unsigned* __restrict__ needb = user ? g_needb_u : g_needb_s;
    const float* __restrict__ emb = user ? uemb : semb;
    const float* __restrict__ wl  = user ? g_wl_u : g_wl_s;
    const float* __restrict__ er  = user ? g_er_u : g_er_s;
    float* acc = user ? g_acc_u : g_acc_s;
    float* den = user ? g_den_u : g_den_s;
    int vb   = user ? blockIdx.x : blockIdx.x - splitBlk;
    int nblk = user ? splitBlk : gridDim.x - splitBlk;

    int tid = threadIdx.x;
    int wid = tid >> 5, l = tid & 31;
    int hl = l & 15;
    int lq = hl * 4;

    float wl00 = __ldg(&wl[(lq+0)*2 + 0]);
    float wl01 = __ldg(&wl[(lq+1)*2 + 0]);
    float wl02 = __ldg(&wl[(lq+2)*2 + 0]);
    float wl03 = __ldg(&wl[(lq+3)*2 + 0]);
    float wl10 = __ldg(&wl[(lq+0)*2 + 1]);
    float wl11 = __ldg(&wl[(lq+1)*2 + 1]);
    float wl12 = __ldg(&wl[(lq+2)*2 + 1]);
    float wl13 = __ldg(&wl[(lq+3)*2 + 1]);

    long long gwarp = (long long)vb*8 + wid;
    long long nwarp = (long long)nblk*8;

    for (long long base = gwarp*32; base < E; base += nwarp*32) {
        long long i = base + l;
        int d = 0, s = 0; bool m = false;
        if (i < E) {
            d = dst[i];
            m = (__ldg(&needb[d >> 5]) >> (d & 31)) & 1u;
        }
        unsigned bal = __ballot_sync(0xffffffffu, m);
        if (m) s = src[i];

        while (bal) {
            int b0 = __ffs(bal) - 1; bal &= bal - 1;
            bool has1 = (bal != 0);
            int b1 = has1 ? (__ffs(bal) - 1) : b0;
            if (has1) bal &= bal - 1;

            int myb = (l < 16) ? b0 : b1;
            int sS = __shfl_sync(0xffffffffu, s, myb);
            int dD = __shfl_sync(0xffffffffu, d, myb);

            float4 e = *(const float4*)&emb[(long long)sS * DIMK + lq];
            float2 erv = *(const float2*)&er[dD*NH];

            float p0 = e.x*wl00 + e.y*wl01 + e.z*wl02 + e.w*wl03;
            float p1 = e.x*wl10 + e.y*wl11 + e.z*wl12 + e.w*wl13;
            #pragma unroll
            for (int o = 8; o; o >>= 1) {
                p0 += __shfl_xor_sync(0xffffffffu, p0, o);
                p1 += __shfl_xor_sync(0xffffffffu, p1, o);
            }
            float a0 = p0 + erv.x;
            float a1 = p1 + erv.y;
            a0 = a0 > 0.f ? a0 : 0.2f * a0;
            a1 = a1 > 0.f ? a1 : 0.2f * a1;
            float x0 = __expf(a0);
            float x1 = __expf(a1);

            if ((l < 16) | has1) {
                red4(&acc[dD*HD + lq],        x0*e.x, x0*e.y, x0*e.z, x0*e.w);
                red4(&acc[dD*HD + DIMK + lq], x1*e.x, x1*e.y, x1*e.z, x1*e.w);
                if (hl == 0) {
                    atomicAdd(&den[dD*NH + 0], x0);
                    atomicAdd(&den[dD*NH + 1], x1);
                }
            }
        }
    }
}

// ---------------- k_tail: 64 rows/block, 512 thr, f32x2 packed FFMA ------------
__global__ void __launch_bounds__(TTHREADS) k_tail(
        const int* __restrict__ uidx, const int* __restrict__ sidx,
        const float* __restrict__ uemb, const float* __restrict__ semb,
        const float* __restrict__ uW, const float* __restrict__ sW,
        const float* __restrict__ ubias, const float* __restrict__ ulng, const float* __restrict__ ulnb,
        const float* __restrict__ sbias, const float* __restrict__ slng, const float* __restrict__ slnb,
        const float* __restrict__ W1, const float* __restrict__ b1,
        const float* __restrict__ g1, const float* __restrict__ bb1,
        const float* __restrict__ W2, const float* __restrict__ b2,
        const float* __restrict__ g2, const float* __restrict__ bb2,
        const float* __restrict__ W3, const float* __restrict__ b3,
        float* __restrict__ out) {
    extern __shared__ float sm[];
    float* As   = sm;                    // TROWS*HD        (32 KB)
    float* xs   = As + TROWS*HD;         // TROWS*HD        (32 KB)
    float* Wbuf = xs + TROWS*HD;         // WFULL           (32 KB)
    int* nodes  = (int*)(Wbuf + WFULL);  // 2*TROWS

    int tid = threadIdx.x;
    int w = tid >> 5, l = tid & 31;      // 16 warps
    int rbase = blockIdx.x * TROWS;
    int r0 = w * 4, c0 = l * 4;
    int h = l >> 4;

    if (tid < TROWS)        nodes[tid] = uidx[rbase + tid];
    else if (tid < 2*TROWS) nodes[tid] = sidx[rbase + tid - TROWS];
    __syncthreads();

    // ================= GAT finalize per side =================
    #pragma unroll 1
    for (int side = 0; side < 2; side++) {
        const float* accp = side ? g_acc_s : g_acc_u;
        const float* denp = side ? g_den_s : g_den_u;
        const float* W    = side ? sW : uW;
        const float* bias = side ? sbias : ubias;
        const float* lng  = side ? slng : ulng;
        const float* lnb  = side ? slnb : ulnb;
        const float* emb  = side ? semb : uemb;

        for (int i = tid; i < TROWS*(HD/4); i += TTHREADS) {
            int rr = i >> 5, cq = i & 31;
            int nd = nodes[side*TROWS + rr];
            float4 a4 = *(const float4*)&accp[(long long)nd*HD + cq*4];
            float inv = __fdividef(1.f, denp[nd*NH + (cq >> 4)]);
            *(float4*)&As[rr*HD + cq*4] = make_float4(a4.x*inv, a4.y*inv, a4.z*inv, a4.w*inv);
        }
        #pragma unroll
        for (int c = 0; c < 4; c++)
            *(float4*)&Wbuf[c*2048 + tid*4] = *(const float4*)&W[c*2048 + tid*4];
        __syncthreads();

        unsigned long long a01[4] = {0ull,0ull,0ull,0ull};
        unsigned long long a23[4] = {0ull,0ull,0ull,0ull};
        #pragma unroll 8
        for (int k = 0; k < DIMK; k++) {
            int ka = h*DIMK + k;
            float4 wv = *(const float4*)&Wbuf[k*HD + c0];
            unsigned long long w01 = pack2(wv.x, wv.y);
            unsigned long long w23 = pack2(wv.z, wv.w);
            #pragma unroll
            for (int r = 0; r < 4; r++) {
                float a = As[(r0+r)*HD + ka];
                unsigned long long aa = pack2(a, a);
                ffma2(a01[r], aa, w01);
                ffma2(a23[r], aa, w23);
            }
        }

        float4 bv = *(const float4*)&bias[c0];
        float4 gv = *(const float4*)&lng[c0];
        float4 bb = *(const float4*)&lnb[c0];
        #pragma unroll
        for (int i = 0; i < 4; i++) {
            float2 p01 = unpack2(a01[i]);
            float2 p23 = unpack2(a23[i]);
            float v0 = p01.x + bv.x, v1 = p01.y + bv.y;
            float v2 = p23.x + bv.z, v3 = p23.y + bv.w;
            float sum = v0+v1+v2+v3;
            #pragma unroll
            for (int o = 16; o; o >>= 1) sum += __shfl_xor_sync(0xffffffffu, sum, o);
            float mean = sum * (1.f/HD);
            float d0 = v0-mean, d1 = v1-mean, d2 = v2-mean, d3 = v3-mean;
            float sq = d0*d0 + d1*d1 + d2*d2 + d3*d3;
            #pragma unroll
            for (int o = 16; o; o >>= 1) sq += __shfl_xor_sync(0xffffffffu, sq, o);
            float rstd = rsqrtf(sq * (1.f/HD) + 1e-5f);
            float n0 = d0*rstd*gv.x + bb.x;
            float n1 = d1*rstd*gv.y + bb.y;
            float n2 = d2*rstd*gv.z + bb.z;
            float n3 = d3*rstd*gv.w + bb.w;
            n0 = n0 > 0.f ? n0 : (__expf(n0) - 1.f);   // ELU
            n1 = n1 > 0.f ? n1 : (__expf(n1) - 1.f);
            n2 = n2 > 0.f ? n2 : (__expf(n2) - 1.f);
            n3 = n3 > 0.f ? n3 : (__expf(n3) - 1.f);
            float m0 = __shfl_xor_sync(0xffffffffu, n0, 16);
            float m1 = __shfl_xor_sync(0xffffffffu, n1, 16);
            float m2 = __shfl_xor_sync(0xffffffffu, n2, 16);
            float m3 = __shfl_xor_sync(0xffffffffu, n3, 16);
            if (l < 16) {
                int nd = nodes[side*TROWS + r0 + i];
                float4 e4 = *(const float4*)&emb[(long long)nd*DIMK + c0];
                float* xr = &xs[(r0+i)*HD + side*DIMK + c0];
                xr[0] = 0.5f*(n0+m0) + e4.x;
                xr[1] = 0.5f*(n1+m1) + e4.y;
                xr[2] = 0.5f*(n2+m2) + e4.z;
                xr[3] = 0.5f*(n3+m3) + e4.w;
            }
        }
        __syncthreads();   // As/Wbuf reuse safety for next phase
    }

    // ================= MLP: 128->128->128->1 =================
    const float* Wp[2]  = {W1, W2};
    const float* bp[2]  = {b1, b2};
    const float* gp[2]  = {g1, g2};
    const float* bbp[2] = {bb1, bb2};
    float val[4][4];

    #pragma unroll 1
    for (int layer = 0; layer < 2; layer++) {
        const float* W = Wp[layer];
        unsigned long long a01[4] = {0ull,0ull,0ull,0ull};
        unsigned long long a23[4] = {0ull,0ull,0ull,0ull};
        #pragma unroll 1
        for (int kc = 0; kc < 2; kc++) {           // two 64-row halves of W
            #pragma unroll
            for (int c = 0; c < 4; c++)
                *(float4*)&Wbuf[c*2048 + tid*4] = *(const float4*)&W[kc*WFULL + c*2048 + tid*4];
            __syncthreads();
            #pragma unroll 4
            for (int k4 = 0; k4 < DIMK; k4 += 4) {
                float4 A0 = *(const float4*)&xs[(r0+0)*HD + kc*DIMK + k4];
                float4 A1 = *(const float4*)&xs[(r0+1)*HD + kc*DIMK + k4];
                float4 A2 = *(const float4*)&xs[(r0+2)*HD + kc*DIMK + k4];
                float4 A3 = *(const float4*)&xs[(r0+3)*HD + kc*DIMK + k4];
                #pragma unroll
                for (int kk = 0; kk < 4; kk++) {
                    float4 wv = *(const float4*)&Wbuf[(k4+kk)*HD + c0];
                    unsigned long long w01 = pack2(wv.x, wv.y);
                    unsigned long long w23 = pack2(wv.z, wv.w);
                    float e0 = FCMP(A0,kk), e1 = FCMP(A1,kk), e2 = FCMP(A2,kk), e3 = FCMP(A3,kk);
                    unsigned long long aa0 = pack2(e0, e0);
                    unsigned long long aa1 = pack2(e1, e1);
                    unsigned long long aa2 = pack2(e2, e2);
                    unsigned long long aa3 = pack2(e3, e3);
                    ffma2(a01[0], aa0, w01); ffma2(a23[0], aa0, w23);
                    ffma2(a01[1], aa1, w01); ffma2(a23[1], aa1, w23);
                    ffma2(a01[2], aa2, w01); ffma2(a23[2], aa2, w23);
                    ffma2(a01[3], aa3, w01); ffma2(a23[3], aa3, w23);
                }
            }
            __syncthreads();                       // before Wbuf overwrite
        }

        float4 bv  = *(const float4*)&bp[layer][c0];
        float4 gv  = *(const float4*)&gp[layer][c0];
        float4 bbv = *(const float4*)&bbp[layer][c0];
        #pragma unroll
        for (int i = 0; i < 4; i++) {
            float2 p01 = unpack2(a01[i]);
            float2 p23 = unpack2(a23[i]);
            float a0 = p01.x + bv.x, a1 = p01.y + bv.y;
            float a2 = p23.x + bv.z, a3 = p23.y + bv.w;
            float sum = a0 + a1 + a2 + a3;
            #pragma unroll
            for (int o = 16; o; o >>= 1) sum += __shfl_xor_sync(0xffffffffu, sum, o);
            float mean = sum * (1.f/HD);
            float d0 = a0-mean, d1 = a1-mean, d2 = a2-mean, d3 = a3-mean;
            float sq = d0*d0 + d1*d1 + d2*d2 + d3*d3;
            #pragma unroll
            for (int o = 16; o; o >>= 1) sq += __shfl_xor_sync(0xffffffffu, sq, o);
            float rstd = rsqrtf(sq * (1.f/HD) + 1e-5f);
            float v0 = fmaxf(d0*rstd*gv.x + bbv.x, 0.f);
            float v1 = fmaxf(d1*rstd*gv.y + bbv.y, 0.f);
            float v2 = fmaxf(d2*rstd*gv.z + bbv.z, 0.f);
            float v3 = fmaxf(d3*rstd*gv.w + bbv.w, 0.f);
            val[i][0] = v0; val[i][1] = v1; val[i][2] = v2; val[i][3] = v3;
        }
        if (layer == 0) {
            #pragma unroll
            for (int i = 0; i < 4; i++) {
                float* xr = &xs[(r0+i)*HD + c0];
                xr[0] = val[i][0]; xr[1] = val[i][1]; xr[2] = val[i][2]; xr[3] = val[i][3];
            }
            __syncthreads();
        }
    }

    float4 w3 = *(const float4*)&W3[c0];
    float bias3 = b3[0];
    #pragma unroll
    for (int i = 0; i < 4; i++) {
        float p = val[i][0]*w3.x + val[i][1]*w3.y + val[i][2]*w3.z + val[i][3]*w3.w;
        #pragma unroll
        for (int o = 16; o; o >>= 1) p += __shfl_xor_sync(0xffffffffu, p, o);
        if (l == 0) out[rbase + r0 + i] = 1.f / (1.f + __expf(-(p + bias3)));
    }
}

// ---------------- launch --------------------------------------------------------
extern "C" void kernel_launch(void* const* d_in, const int* in_sizes, int n_in,
                              void* d_out, int out_size) {
    const int*   uidx  = (const int*)  d_in[0];
    const int*   sidx  = (const int*)  d_in[1];
    const int*   usrc  = (const int*)  d_in[2];
    const int*   udst  = (const int*)  d_in[3];
    const int*   ssrc  = (const int*)  d_in[4];
    const int*   sdst  = (const int*)  d_in[5];
    const float* uemb  = (const float*)d_in[6];
    const float* semb  = (const float*)d_in[7];
    const float* uW    = (const float*)d_in[8];
    const float* ual   = (const float*)d_in[9];
    const float* uar   = (const float*)d_in[10];
    const float* ubias = (const float*)d_in[11];
    const float* ulng  = (const float*)d_in[12];
    const float* ulnb  = (const float*)d_in[13];
    const float* sW    = (const float*)d_in[14];
    const float* sal   = (const float*)d_in[15];
    const float* sar   = (const float*)d_in[16];
    const float* sbias = (const float*)d_in[17];
    const float* slng  = (const float*)d_in[18];
    const float* slnb  = (const float*)d_in[19];
    const float* W1    = (const float*)d_in[20];
    const float* b1    = (const float*)d_in[21];
    const float* g1    = (const float*)d_in[22];
    const float* bb1   = (const float*)d_in[23];
    const float* W2    = (const float*)d_in[24];
    const float* b2    = (const float*)d_in[25];
    const float* g2    = (const float*)d_in[26];
    const float* bb2   = (const float*)d_in[27];
    const float* W3    = (const float*)d_in[28];
    const float* b3    = (const float*)d_in[29];
    float* out = (float*)d_out;

    int B  = in_sizes[0];
    int Eu = in_sizes[2];
    int Es = in_sizes[4];

    k_init<<<33, 256>>>(uW, ual, uar, sW, sal, sar);
    k_mark<<<B/8, 256>>>(uidx, sidx, uemb, semb);
    {
        int gu = 592, gs = 1184;   // split ~ Eu : Es
        k_edge_all<<<gu + gs, 256>>>(usrc, udst, Eu, ssrc, sdst, Es,
                                     uemb, semb, gu);
    }
    {
        const int smemBytes = (TROWS*HD + TROWS*HD + WFULL) * 4 + 2*TROWS*4;
        cudaFuncSetAttribute(k_tail, cudaFuncAttributeMaxDynamicSharedMemorySize, smemBytes);
        k_tail<<<(B + TROWS - 1)/TROWS, TTHREADS, smemBytes>>>(
            uidx, sidx, uemb, semb, uW, sW,
            ubias, ulng, ulnb, sbias, slng, slnb,
            W1, b1, g1, bb1, W2, b2, g2, bb2, W3, b3, out);
    }
}